// round 5
// baseline (speedup 1.0000x reference)
#include <cuda_runtime.h>
#include <math.h>

#define Bb 64
#define Hh 256
#define Ll 1024
#define Nn 64
#define BHL (Bb*Hh*Ll)

// ---------------- scratch (device globals; no allocs allowed) ----------------
__device__ float g_x1[BHL];        // post-AdaLN x (residual source)
__device__ float g_z[BHL];         // z (pre-norm out) ; later reused for gated g
__device__ float g_yg[BHL];        // gelu(conv out + D*z)
__device__ float g_ss[Bb*2048];    // scale(0:1024) / shift(1024:2048) per batch
__device__ float g_semb[Bb*1024];  // silu(sin/cos emb)
__device__ float g_ktime[Hh*2048]; // time-domain bidirectional kernel
__device__ float g_khr[Hh*2048];   // full complex spectrum of k (re)
__device__ float g_khi[Hh*2048];   // (im)
__device__ float g_part[8*Bb*2048];// ada split-K partials
__device__ float2 g_tw[1024];      // FFT twiddles exp(-i*pi*k/1024)

// ---------------- helpers ----------------
__device__ __forceinline__ float geluf(float x) {
    return 0.5f * x * (1.0f + erff(x * 0.70710678118654752440f));
}
__device__ __forceinline__ float gatef(float x) {
    // tanh(x)*sigmoid(x) with one exp: t=e^-x, tanh=(1-t^2)/(1+t^2), sig=1/(1+t)
    float t  = __expf(-fmaxf(x, -30.0f));
    float t2 = t * t;
    return ((1.0f - t2) / (1.0f + t2)) * (1.0f / (1.0f + t));
}

// ---- packed f32x2 ops (FFMA2 — only reachable via PTX) ----
typedef unsigned long long ull;
__device__ __forceinline__ ull f2pack(float lo, float hi) {
    ull r;
    asm("mov.b64 %0, {%1, %2};" : "=l"(r) : "f"(lo), "f"(hi));
    return r;
}
__device__ __forceinline__ void f2unpack(ull v, float &lo, float &hi) {
    asm("mov.b64 {%0, %1}, %2;" : "=f"(lo), "=f"(hi) : "l"(v));
}
__device__ __forceinline__ void ffma2(ull &d, ull a, ull b) {
    asm("fma.rn.f32x2 %0, %1, %2, %0;" : "+l"(d) : "l"(a), "l"(b));
}

// ---------------- twiddle table ----------------
__global__ void k_twfill() {
    int i = blockIdx.x * 256 + threadIdx.x;
    float ang = -3.14159265358979323846f * (float)i * (1.0f / 1024.0f);
    float sn, cs; sincosf(ang, &sn, &cs);
    g_tw[i] = make_float2(cs, sn);
}

// ---------------- sinusoidal embedding + silu ----------------
__global__ void __launch_bounds__(256) k_semb(const int* __restrict__ t) {
    int b = blockIdx.x;
    float tf = (float)t[b];
    const float cfr = (float)(-9.210340371976184 / 511.0);   // -log(10000)/(half-1)
    #pragma unroll
    for (int r = 0; r < 4; r++) {
        int i = threadIdx.x + (r << 8);
        float v;
        if (i < 512) v = sinf(tf * expf((float)i * cfr));
        else         v = cosf(tf * expf((float)(i - 512) * cfr));
        float sg = 1.0f / (1.0f + expf(-v));
        g_semb[b * 1024 + i] = v * sg;
    }
}

// ---------------- emb @ ada_w.T  (split-K partials) ----------------
__global__ void __launch_bounds__(256) k_ada_gemm(const float* __restrict__ W) {
    __shared__ float Ws[64][32];   // [k][o]
    __shared__ float Eb[64][64];   // [b][k]
    int o0 = blockIdx.x * 32;
    int kc = blockIdx.y;
    int tid = threadIdx.x;
    int o  = tid & 31;
    int bg = tid >> 5;      // 0..7, owns 8 batches
    float acc[8];
    #pragma unroll
    for (int j = 0; j < 8; j++) acc[j] = 0.f;

    for (int kk = kc * 128; kk < kc * 128 + 128; kk += 64) {
        {
            int oo = tid >> 3;       // 0..31
            int kq = tid & 7;        // 0..7
            const float* src = &W[(size_t)(o0 + oo) * 1024 + kk + kq * 8];
            float4 a = *(const float4*)(src);
            float4 c = *(const float4*)(src + 4);
            int kb = kq * 8;
            Ws[kb+0][oo] = a.x; Ws[kb+1][oo] = a.y; Ws[kb+2][oo] = a.z; Ws[kb+3][oo] = a.w;
            Ws[kb+4][oo] = c.x; Ws[kb+5][oo] = c.y; Ws[kb+6][oo] = c.z; Ws[kb+7][oo] = c.w;
        }
        #pragma unroll
        for (int r = 0; r < 16; r++) {
            int e = tid + (r << 8);
            int bq = e >> 6, k = e & 63;
            Eb[bq][k] = g_semb[bq * 1024 + kk + k];
        }
        __syncthreads();
        #pragma unroll 8
        for (int k = 0; k < 64; k++) {
            float wv = Ws[k][o];
            #pragma unroll
            for (int j = 0; j < 8; j++)
                acc[j] += Eb[bg * 8 + j][k] * wv;
        }
        __syncthreads();
    }
    #pragma unroll
    for (int j = 0; j < 8; j++)
        g_part[((size_t)kc * 64 + bg * 8 + j) * 2048 + o0 + o] = acc[j];
}

__global__ void __launch_bounds__(256) k_ada_reduce(const float* __restrict__ bias) {
    int idx = blockIdx.x * 256 + threadIdx.x;   // 64*2048
    int b = idx >> 11, o = idx & 2047;
    float s = bias[o];
    #pragma unroll
    for (int kc = 0; kc < 8; kc++)
        s += g_part[((size_t)kc * 64 + b) * 2048 + o];
    g_ss[b * 2048 + o] = s;
}

// ---------------- AdaLayerNorm over L: x1 = ln(x)*(1+scale)+shift ----------------
__global__ void __launch_bounds__(256) k_adaln(const float* __restrict__ x) {
    int bh = blockIdx.x;
    int b = bh >> 8;
    int tid = threadIdx.x;
    const float4* xr = (const float4*)(x + (size_t)bh * 1024);
    float4 v = xr[tid];
    float s = v.x + v.y + v.z + v.w;
    float q = v.x*v.x + v.y*v.y + v.z*v.z + v.w*v.w;
    #pragma unroll
    for (int o = 16; o; o >>= 1) {
        s += __shfl_down_sync(0xffffffffu, s, o);
        q += __shfl_down_sync(0xffffffffu, q, o);
    }
    __shared__ float as_[8], aq_[8];
    if ((tid & 31) == 0) { as_[tid >> 5] = s; aq_[tid >> 5] = q; }
    __syncthreads();
    float S = 0.f, Q = 0.f;
    #pragma unroll
    for (int i = 0; i < 8; i++) { S += as_[i]; Q += aq_[i]; }
    float m  = S * (1.0f / 1024.0f);
    float va = Q * (1.0f / 1024.0f) - m * m;
    float rs = rsqrtf(va + 1e-5f);
    const float4* sc = (const float4*)(g_ss + b * 2048);
    const float4* sh = (const float4*)(g_ss + b * 2048 + 1024);
    float4 a = sc[tid], d = sh[tid];
    float4 o4;
    o4.x = (v.x - m) * rs * (1.0f + a.x) + d.x;
    o4.y = (v.y - m) * rs * (1.0f + a.y) + d.y;
    o4.z = (v.z - m) * rs * (1.0f + a.z) + d.z;
    o4.w = (v.w - m) * rs * (1.0f + a.w) + d.w;
    ((float4*)(g_x1 + (size_t)bh * 1024))[tid] = o4;
}

// ---------------- channel LayerNorm over H ----------------
__global__ void __launch_bounds__(256) k_chanln(const float* __restrict__ nw,
                                                const float* __restrict__ nb) {
    int b = blockIdx.x;
    int l0 = blockIdx.y * 32;
    int tid = threadIdx.x;
    int lx = tid & 31, hp = tid >> 5;
    float v[32];
    float s = 0.f, q = 0.f;
    const float* base = g_x1 + ((size_t)b * Hh) * Ll + l0 + lx;
    #pragma unroll 8
    for (int k = 0; k < 32; k++) {
        float xv = base[(size_t)(hp * 32 + k) * Ll];
        v[k] = xv; s += xv; q += xv * xv;
    }
    __shared__ float ps[8][32], pq[8][32];
    __shared__ float mean_[32], rstd_[32];
    ps[hp][lx] = s; pq[hp][lx] = q;
    __syncthreads();
    if (tid < 32) {
        float S = 0.f, Q = 0.f;
        #pragma unroll
        for (int p = 0; p < 8; p++) { S += ps[p][tid]; Q += pq[p][tid]; }
        float m  = S * (1.0f / 256.0f);
        float va = Q * (1.0f / 256.0f) - m * m;
        mean_[tid] = m; rstd_[tid] = rsqrtf(va + 1e-5f);
    }
    __syncthreads();
    float m = mean_[lx], r = rstd_[lx];
    float* zb = g_z + ((size_t)b * Hh) * Ll + l0 + lx;
    #pragma unroll 8
    for (int k = 0; k < 32; k++) {
        int h = hp * 32 + k;
        zb[(size_t)h * Ll] = (v[k] - m) * r * nw[h] + nb[h];
    }
}

// ---------------- SSM kernel (time domain, bidirectional assembled) ----------------
__global__ void __launch_bounds__(256) k_ssm(const float* __restrict__ log_dt,
                                             const float* __restrict__ A_re,
                                             const float* __restrict__ A_im,
                                             const float* __restrict__ C_re,
                                             const float* __restrict__ C_im) {
    __shared__ float pre[6][64]; // dtA_re, dtA_im, c0r, c0i, c1r, c1i
    int h = blockIdx.x, tid = threadIdx.x;
    if (tid < 64) {
        int n = tid;
        float dt  = expf(log_dt[h]);
        float are = -expf(A_re[h * 64 + n]);
        float aim = A_im[h * 64 + n];
        float dre = dt * are, dim = dt * aim;
        float er = expf(dre);
        float sn, cs; sincosf(dim, &sn, &cs);
        float dAr = er * cs, dAi = er * sn;
        float numr = dAr - 1.0f, numi = dAi;
        float den = are * are + aim * aim;
        float fr = (numr * are + numi * aim) / den;
        float fi = (numi * are - numr * aim) / den;
        float c0re = C_re[h * 64 + n],             c0im = C_im[h * 64 + n];
        float c1re = C_re[Hh * 64 + h * 64 + n],   c1im = C_im[Hh * 64 + h * 64 + n];
        pre[0][n] = dre; pre[1][n] = dim;
        pre[2][n] = c0re * fr - c0im * fi; pre[3][n] = c0re * fi + c0im * fr;
        pre[4][n] = c1re * fr - c1im * fi; pre[5][n] = c1re * fi + c1im * fr;
    }
    __syncthreads();
    #pragma unroll
    for (int qq = 0; qq < 4; qq++) {
        int l = tid + (qq << 8);
        float lf = (float)l;
        float k0 = 0.f, k1 = 0.f;
        #pragma unroll 4
        for (int n = 0; n < 64; n++) {
            float pr = pre[0][n] * lf, pi = pre[1][n] * lf;
            float e = expf(pr);
            float sn, cs; sincosf(pi, &sn, &cs);
            float vr = e * cs, vi = e * sn;
            k0 += pre[2][n] * vr - pre[3][n] * vi;
            k1 += pre[4][n] * vr - pre[5][n] * vi;
        }
        g_ktime[h * 2048 + l]        = 2.0f * k0;
        g_ktime[h * 2048 + 2047 - l] = 2.0f * k1;
    }
}

// ---------------- radix-8 Stockham FFT, N=2048, 256 threads ----------------
// Stockham: out[R*m*p + r + j*m] = w_N^{j*m*p} * sum_s in[m*p + r + s*N/R] * w_R^{j*s}
// 3 radix-8 stages (m=1,8,64) + 1 twiddle-free radix-4 stage (m=512, p=0).
__device__ __forceinline__ void fft2048_r8(float*& sr, float*& si, float*& dr, float*& di) {
    const float Cq = 0.70710678118654752440f;
    #pragma unroll
    for (int lm = 0; lm < 9; lm += 3) {   // m = 1, 8, 64
        const int m = 1 << lm;
        int i = threadIdx.x;              // one butterfly per thread
        int p = i >> lm;
        int r = i & (m - 1);
        float xr[8], xi[8];
        #pragma unroll
        for (int s = 0; s < 8; s++) { xr[s] = sr[i + (s << 8)]; xi[s] = si[i + (s << 8)]; }
        // layer 1 (distance 4), with w8^s twiddles on the odd branch
        float pr_[4], pi_[4], qr[4], qi[4];
        #pragma unroll
        for (int s = 0; s < 4; s++) {
            pr_[s] = xr[s] + xr[s+4]; pi_[s] = xi[s] + xi[s+4];
            qr[s]  = xr[s] - xr[s+4]; qi[s]  = xi[s] - xi[s+4];
        }
        { float a=qr[1], b=qi[1]; qr[1] = Cq*(a+b); qi[1] = Cq*(b-a); }   // * w8
        { float a=qr[2], b=qi[2]; qr[2] = b;        qi[2] = -a;       }   // * -i
        { float a=qr[3], b=qi[3]; qr[3] = Cq*(b-a); qi[3] = -Cq*(a+b); }  // * w8^3
        float Xr[8], Xi[8];
        { // DFT4 on p -> even outputs
            float r0r=pr_[0]+pr_[2], r0i=pi_[0]+pi_[2];
            float r1r=pr_[0]-pr_[2], r1i=pi_[0]-pi_[2];
            float r2r=pr_[1]+pr_[3], r2i=pi_[1]+pi_[3];
            float t3r=pr_[1]-pr_[3], t3i=pi_[1]-pi_[3];
            float r3r=t3i, r3i=-t3r;
            Xr[0]=r0r+r2r; Xi[0]=r0i+r2i;
            Xr[2]=r1r+r3r; Xi[2]=r1i+r3i;
            Xr[4]=r0r-r2r; Xi[4]=r0i-r2i;
            Xr[6]=r1r-r3r; Xi[6]=r1i-r3i;
        }
        { // DFT4 on q -> odd outputs
            float r0r=qr[0]+qr[2], r0i=qi[0]+qi[2];
            float r1r=qr[0]-qr[2], r1i=qi[0]-qi[2];
            float r2r=qr[1]+qr[3], r2i=qi[1]+qi[3];
            float t3r=qr[1]-qr[3], t3i=qi[1]-qi[3];
            float r3r=t3i, r3i=-t3r;
            Xr[1]=r0r+r2r; Xi[1]=r0i+r2i;
            Xr[3]=r1r+r3r; Xi[3]=r1i+r3i;
            Xr[5]=r0r-r2r; Xi[5]=r0i-r2i;
            Xr[7]=r1r-r3r; Xi[7]=r1i-r3i;
        }
        // output twiddles w^j, w = tw[m*p]
        float2 w = g_tw[m * p];
        float wjr = 1.f, wji = 0.f;
        int o = ((m * p) << 3) + r;
        dr[o] = Xr[0]; di[o] = Xi[0];
        #pragma unroll
        for (int j = 1; j < 8; j++) {
            float nr = wjr * w.x - wji * w.y;
            wji = wji * w.x + wjr * w.y;
            wjr = nr;
            dr[o + j * m] = Xr[j] * wjr - Xi[j] * wji;
            di[o + j * m] = Xi[j] * wjr + Xr[j] * wji;
        }
        __syncthreads();
        float* tp; tp=sr;sr=dr;dr=tp; tp=si;si=di;di=tp;
    }
    // final radix-4, m=512, p=0 (twiddle-free): out[r + j*512] = DFT4_s in[r + 512 s]
    #pragma unroll
    for (int q = 0; q < 2; q++) {
        int r = threadIdx.x + (q << 8);   // 0..511
        float a0r=sr[r],      a0i=si[r];
        float a1r=sr[r+512],  a1i=si[r+512];
        float a2r=sr[r+1024], a2i=si[r+1024];
        float a3r=sr[r+1536], a3i=si[r+1536];
        float r0r=a0r+a2r, r0i=a0i+a2i;
        float r1r=a0r-a2r, r1i=a0i-a2i;
        float r2r=a1r+a3r, r2i=a1i+a3i;
        float t3r=a1r-a3r, t3i=a1i-a3i;
        float r3r=t3i, r3i=-t3r;
        dr[r]      = r0r+r2r; di[r]      = r0i+r2i;
        dr[r+512]  = r1r+r3r; di[r+512]  = r1i+r3i;
        dr[r+1024] = r0r-r2r; di[r+1024] = r0i-r2i;
        dr[r+1536] = r1r-r3r; di[r+1536] = r1i-r3i;
    }
    __syncthreads();
    float* tp; tp=sr;sr=dr;dr=tp; tp=si;si=di;di=tp;
}

// ---------------- FFT of kernel rows (pack 2 h per block, unpack to full spectra) ----------------
__global__ void __launch_bounds__(256) k_kfft() {
    __shared__ float bAr[2048], bAi[2048], bBr[2048], bBi[2048];
    int tid = threadIdx.x;
    int h0 = blockIdx.x * 2, h1 = h0 + 1;
    #pragma unroll
    for (int qq = 0; qq < 8; qq++) {
        int idx = tid + (qq << 8);
        bAr[idx] = g_ktime[h0 * 2048 + idx];
        bAi[idx] = g_ktime[h1 * 2048 + idx];
    }
    __syncthreads();
    float *sr = bAr, *si = bAi, *dr = bBr, *di = bBi;
    fft2048_r8(sr, si, dr, di);
    #pragma unroll
    for (int qq = 0; qq < 8; qq++) {
        int f = tid + (qq << 8);
        int fr2 = (2048 - f) & 2047;
        float ur = sr[f],  ui = si[f];
        float vr = sr[fr2], vi = -si[fr2];
        g_khr[h0 * 2048 + f] = 0.5f * (ur + vr);
        g_khi[h0 * 2048 + f] = 0.5f * (ui + vi);
        g_khr[h1 * 2048 + f] = 0.5f * (ui - vi);
        g_khi[h1 * 2048 + f] = -0.5f * (ur - vr);
    }
}

// ---------------- main conv: 2 batch rows packed; epilogue +D*z, gelu ----------------
__global__ void __launch_bounds__(256) k_conv(const float* __restrict__ Dp) {
    __shared__ float bAr[2048], bAi[2048], bBr[2048], bBi[2048];
    int tid = threadIdx.x;
    int h  = blockIdx.x;
    int pb = blockIdx.y;
    const float* za = g_z + ((size_t)(2 * pb) * Hh + h) * Ll;
    const float* zb = za + (size_t)Hh * Ll;
    float ra[4], rb[4];
    #pragma unroll
    for (int qq = 0; qq < 4; qq++) {
        int idx = tid + (qq << 8);
        ra[qq] = za[idx]; rb[qq] = zb[idx];
        bAr[idx] = ra[qq]; bAi[idx] = rb[qq];
        bAr[idx + 1024] = 0.f; bAi[idx + 1024] = 0.f;
    }
    __syncthreads();
    float *sr = bAr, *si = bAi, *dr = bBr, *di = bBi;
    fft2048_r8(sr, si, dr, di);
    const float* khr = g_khr + h * 2048;
    const float* khi = g_khi + h * 2048;
    const float inv = 1.0f / 2048.0f;
    #pragma unroll
    for (int qq = 0; qq < 8; qq++) {
        int f = tid + (qq << 8);
        float kr = khr[f], ki = khi[f];
        float ar = sr[f], ai = si[f];
        float pr = ar * kr - ai * ki;
        float pi = ar * ki + ai * kr;
        sr[f] = pr * inv;        // conj + scale for inverse transform
        si[f] = -pi * inv;
    }
    __syncthreads();
    fft2048_r8(sr, si, dr, di);
    float Dh = Dp[h];
    float* ya = g_yg + ((size_t)(2 * pb) * Hh + h) * Ll;
    float* yb = ya + (size_t)Hh * Ll;
    #pragma unroll
    for (int qq = 0; qq < 4; qq++) {
        int idx = tid + (qq << 8);
        float v1 = sr[idx]  + Dh * ra[qq];
        float v2 = -si[idx] + Dh * rb[qq];
        ya[idx] = geluf(v1);
        yb[idx] = geluf(v2);
    }
}

// ---------------- big GEMM with packed f32x2 FMA ----------------
// C[o,l] = W[o,:]@X[:,l] (+bias)(+resid)(activation); 128x128 tile, 8x8/thread.
// mode 0: gate(acc+b+resid) ; mode 1: acc+b+resid ; mode 2: acc+b
__global__ void __launch_bounds__(256) k_gemm(const float* __restrict__ W,
                                              const float* __restrict__ bias,
                                              const float* __restrict__ X,
                                              const float* __restrict__ resid,
                                              float* __restrict__ Yout,
                                              int mode) {
    __shared__ ull   Ws2[16][132];   // [k][o], each entry is the dup pair (w,w)
    __shared__ float Ys[16][136];
    int l0 = blockIdx.x * 128;
    int o0 = blockIdx.y * 128;
    int b  = blockIdx.z;
    int tid = threadIdx.x;
    int ty = tid >> 4, tx = tid & 15;

    ull acc[8][4];
    #pragma unroll
    for (int i = 0; i < 8; i++)
        #pragma unroll
        for (int j = 0; j < 4; j++) acc[i][j] = 0ull;

    // staging thread mapping
    int wo = tid >> 1, wk = (tid & 1) * 8;     // W: row wo, k-offset wk (8 floats)
    int yk = tid >> 4, yl = (tid & 15) * 4;    // X: row yk, cols yl and yl+64

    const float* wptr = &W[(size_t)(o0 + wo) * 256 + wk];
    const float* xptr = &X[((size_t)b * Hh + yk) * Ll + l0 + yl];

    float4 w0 = *(const float4*)(wptr);
    float4 w1 = *(const float4*)(wptr + 4);
    float4 y0 = *(const float4*)(xptr);
    float4 y1 = *(const float4*)(xptr + 64);

    #pragma unroll 1
    for (int it = 0; it < 16; it++) {
        Ws2[wk+0][wo] = f2pack(w0.x, w0.x);
        Ws2[wk+1][wo] = f2pack(w0.y, w0.y);
        Ws2[wk+2][wo] = f2pack(w0.z, w0.z);
        Ws2[wk+3][wo] = f2pack(w0.w, w0.w);
        Ws2[wk+4][wo] = f2pack(w1.x, w1.x);
        Ws2[wk+5][wo] = f2pack(w1.y, w1.y);
        Ws2[wk+6][wo] = f2pack(w1.z, w1.z);
        Ws2[wk+7][wo] = f2pack(w1.w, w1.w);
        *(float4*)&Ys[yk][yl]      = y0;
        *(float4*)&Ys[yk][yl + 64] = y1;
        __syncthreads();
        if (it < 15) {
            const float* wp = wptr + (it + 1) * 16;
            const float* xp = xptr + (size_t)(it + 1) * 16 * Ll;
            w0 = *(const float4*)(wp);
            w1 = *(const float4*)(wp + 4);
            y0 = *(const float4*)(xp);
            y1 = *(const float4*)(xp + 64);
        }
        #pragma unroll
        for (int k = 0; k < 16; k++) {
            ulonglong2 a01 = *(const ulonglong2*)&Ws2[k][ty * 4];
            ulonglong2 a23 = *(const ulonglong2*)&Ws2[k][ty * 4 + 2];
            ulonglong2 a45 = *(const ulonglong2*)&Ws2[k][ty * 4 + 64];
            ulonglong2 a67 = *(const ulonglong2*)&Ws2[k][ty * 4 + 66];
            ulonglong2 b01 = *(const ulonglong2*)&Ys[k][tx * 4];
            ulonglong2 b23 = *(const ulonglong2*)&Ys[k][tx * 4 + 64];
            ull av[8] = {a01.x, a01.y, a23.x, a23.y, a45.x, a45.y, a67.x, a67.y};
            ull bv[4] = {b01.x, b01.y, b23.x, b23.y};
            #pragma unroll
            for (int ii = 0; ii < 8; ii++)
                #pragma unroll
                for (int jp = 0; jp < 4; jp++)
                    ffma2(acc[ii][jp], av[ii], bv[jp]);
        }
        __syncthreads();
    }

    #pragma unroll
    for (int ii = 0; ii < 8; ii++) {
        int o = o0 + ((ii < 4) ? (ty * 4 + ii) : (64 + ty * 4 + ii - 4));
        float bo = bias[o];
        size_t rb = ((size_t)b * Hh + o) * Ll + l0;
        #pragma unroll
        for (int jh = 0; jh < 2; jh++) {
            float f0, f1, f2, f3;
            f2unpack(acc[ii][jh * 2],     f0, f1);
            f2unpack(acc[ii][jh * 2 + 1], f2, f3);
            int lc = jh * 64 + tx * 4;
            float4 res;
            if (mode != 2) res = *(const float4*)&resid[rb + lc];
            else           res = make_float4(0.f, 0.f, 0.f, 0.f);
            float4 r;
            r.x = f0 + bo + res.x;
            r.y = f1 + bo + res.y;
            r.z = f2 + bo + res.z;
            r.w = f3 + bo + res.w;
            if (mode == 0) {
                r.x = gatef(r.x); r.y = gatef(r.y);
                r.z = gatef(r.z); r.w = gatef(r.w);
            }
            *(float4*)&Yout[rb + lc] = r;
        }
    }
}

// ---------------- launch ----------------
extern "C" void kernel_launch(void* const* d_in, const int* in_sizes, int n_in,
                              void* d_out, int out_size) {
    const float* x      = (const float*)d_in[0];
    const int*   t      = (const int*)  d_in[1];
    const float* ada_w  = (const float*)d_in[2];
    const float* ada_b  = (const float*)d_in[3];
    const float* norm_w = (const float*)d_in[4];
    const float* norm_b = (const float*)d_in[5];
    const float* log_dt = (const float*)d_in[6];
    const float* A_re   = (const float*)d_in[7];
    const float* A_im   = (const float*)d_in[8];
    const float* C_re   = (const float*)d_in[9];
    const float* C_im   = (const float*)d_in[10];
    const float* Dp     = (const float*)d_in[11];
    const float* out_w  = (const float*)d_in[12];
    const float* out_b  = (const float*)d_in[13];
    const float* lin1_w = (const float*)d_in[14];
    const float* lin1_b = (const float*)d_in[15];
    const float* lin2_w = (const float*)d_in[16];
    const float* lin2_b = (const float*)d_in[17];
    float* out = (float*)d_out;
    (void)in_sizes; (void)n_in; (void)out_size;

    float *p_x1, *p_z, *p_yg;
    cudaGetSymbolAddress((void**)&p_x1, g_x1);
    cudaGetSymbolAddress((void**)&p_z,  g_z);
    cudaGetSymbolAddress((void**)&p_yg, g_yg);

    k_twfill<<<4, 256>>>();
    k_semb<<<64, 256>>>(t);
    k_ssm<<<256, 256>>>(log_dt, A_re, A_im, C_re, C_im);
    k_kfft<<<128, 256>>>();
    k_ada_gemm<<<dim3(64, 8), 256>>>(ada_w);
    k_ada_reduce<<<512, 256>>>(ada_b);
    k_adaln<<<Bb * Hh, 256>>>(x);
    k_chanln<<<dim3(64, 32), 256>>>(norm_w, norm_b);
    k_conv<<<dim3(256, 32), 256>>>(Dp);
    k_gemm<<<dim3(8, 2, 64), 256>>>(out_w,  out_b,  p_yg, p_x1, p_z,        0);
    k_gemm<<<dim3(8, 2, 64), 256>>>(lin1_w, lin1_b, p_z,  p_x1, out,        1);
    k_gemm<<<dim3(8, 2, 64), 256>>>(lin2_w, lin2_b, p_z,  p_x1, out + BHL,  2);
}

// round 6
// speedup vs baseline: 1.5914x; 1.5914x over previous
#include <cuda_runtime.h>
#include <cuda_bf16.h>
#include <math.h>

#define Bb 64
#define Hh 256
#define Ll 1024
#define Nn 64
#define BHL (Bb*Hh*Ll)

// ---------------- scratch (device globals; no allocs allowed) ----------------
__device__ float g_x1[BHL];        // post-AdaLN x (residual source)
__device__ float g_z[BHL];         // z (pre-norm out) ; later reused for gated g
__device__ float g_yg[BHL];        // gelu(conv out + D*z)
__device__ float g_ss[Bb*2048];    // scale(0:1024) / shift(1024:2048) per batch
__device__ float g_semb[Bb*1024];  // silu(sin/cos emb)
__device__ float g_ktime[Hh*2048]; // time-domain bidirectional kernel
__device__ float g_khr[Hh*2048];   // full complex spectrum of k (re)
__device__ float g_khi[Hh*2048];   // (im)
__device__ float g_part[8*Bb*2048];// ada split-K partials
__device__ float2 g_tw[1024];      // FFT twiddles exp(-i*pi*k/1024)

// ---------------- helpers ----------------
__device__ __forceinline__ float geluf(float x) {
    return 0.5f * x * (1.0f + erff(x * 0.70710678118654752440f));
}
__device__ __forceinline__ float gatef(float x) {
    // tanh(x)*sigmoid(x) with one exp: t=e^-x, tanh=(1-t^2)/(1+t^2), sig=1/(1+t)
    float t  = __expf(-fmaxf(x, -30.0f));
    float t2 = t * t;
    return ((1.0f - t2) / (1.0f + t2)) * (1.0f / (1.0f + t));
}
__device__ __forceinline__ unsigned pckbf(__nv_bfloat16 a, __nv_bfloat16 b) {
    __nv_bfloat162 t; t.x = a; t.y = b;
    return *reinterpret_cast<unsigned*>(&t);
}

// ---------------- twiddle table ----------------
__global__ void k_twfill() {
    int i = blockIdx.x * 256 + threadIdx.x;
    float ang = -3.14159265358979323846f * (float)i * (1.0f / 1024.0f);
    float sn, cs; sincosf(ang, &sn, &cs);
    g_tw[i] = make_float2(cs, sn);
}

// ---------------- sinusoidal embedding + silu ----------------
__global__ void __launch_bounds__(256) k_semb(const int* __restrict__ t) {
    int b = blockIdx.x;
    float tf = (float)t[b];
    const float cfr = (float)(-9.210340371976184 / 511.0);   // -log(10000)/(half-1)
    #pragma unroll
    for (int r = 0; r < 4; r++) {
        int i = threadIdx.x + (r << 8);
        float v;
        if (i < 512) v = sinf(tf * expf((float)i * cfr));
        else         v = cosf(tf * expf((float)(i - 512) * cfr));
        float sg = 1.0f / (1.0f + expf(-v));
        g_semb[b * 1024 + i] = v * sg;
    }
}

// ---------------- emb @ ada_w.T  (split-K partials) ----------------
__global__ void __launch_bounds__(256) k_ada_gemm(const float* __restrict__ W) {
    __shared__ float Ws[64][32];   // [k][o]
    __shared__ float Eb[64][64];   // [b][k]
    int o0 = blockIdx.x * 32;
    int kc = blockIdx.y;
    int tid = threadIdx.x;
    int o  = tid & 31;
    int bg = tid >> 5;      // 0..7, owns 8 batches
    float acc[8];
    #pragma unroll
    for (int j = 0; j < 8; j++) acc[j] = 0.f;

    for (int kk = kc * 128; kk < kc * 128 + 128; kk += 64) {
        {
            int oo = tid >> 3;       // 0..31
            int kq = tid & 7;        // 0..7
            const float* src = &W[(size_t)(o0 + oo) * 1024 + kk + kq * 8];
            float4 a = *(const float4*)(src);
            float4 c = *(const float4*)(src + 4);
            int kb = kq * 8;
            Ws[kb+0][oo] = a.x; Ws[kb+1][oo] = a.y; Ws[kb+2][oo] = a.z; Ws[kb+3][oo] = a.w;
            Ws[kb+4][oo] = c.x; Ws[kb+5][oo] = c.y; Ws[kb+6][oo] = c.z; Ws[kb+7][oo] = c.w;
        }
        #pragma unroll
        for (int r = 0; r < 16; r++) {
            int e = tid + (r << 8);
            int bq = e >> 6, k = e & 63;
            Eb[bq][k] = g_semb[bq * 1024 + kk + k];
        }
        __syncthreads();
        #pragma unroll 8
        for (int k = 0; k < 64; k++) {
            float wv = Ws[k][o];
            #pragma unroll
            for (int j = 0; j < 8; j++)
                acc[j] += Eb[bg * 8 + j][k] * wv;
        }
        __syncthreads();
    }
    #pragma unroll
    for (int j = 0; j < 8; j++)
        g_part[((size_t)kc * 64 + bg * 8 + j) * 2048 + o0 + o] = acc[j];
}

__global__ void __launch_bounds__(256) k_ada_reduce(const float* __restrict__ bias) {
    int idx = blockIdx.x * 256 + threadIdx.x;   // 64*2048
    int b = idx >> 11, o = idx & 2047;
    float s = bias[o];
    #pragma unroll
    for (int kc = 0; kc < 8; kc++)
        s += g_part[((size_t)kc * 64 + b) * 2048 + o];
    g_ss[b * 2048 + o] = s;
}

// ---------------- AdaLayerNorm over L: x1 = ln(x)*(1+scale)+shift ----------------
__global__ void __launch_bounds__(256) k_adaln(const float* __restrict__ x) {
    int bh = blockIdx.x;
    int b = bh >> 8;
    int tid = threadIdx.x;
    const float4* xr = (const float4*)(x + (size_t)bh * 1024);
    float4 v = xr[tid];
    float s = v.x + v.y + v.z + v.w;
    float q = v.x*v.x + v.y*v.y + v.z*v.z + v.w*v.w;
    #pragma unroll
    for (int o = 16; o; o >>= 1) {
        s += __shfl_down_sync(0xffffffffu, s, o);
        q += __shfl_down_sync(0xffffffffu, q, o);
    }
    __shared__ float as_[8], aq_[8];
    if ((tid & 31) == 0) { as_[tid >> 5] = s; aq_[tid >> 5] = q; }
    __syncthreads();
    float S = 0.f, Q = 0.f;
    #pragma unroll
    for (int i = 0; i < 8; i++) { S += as_[i]; Q += aq_[i]; }
    float m  = S * (1.0f / 1024.0f);
    float va = Q * (1.0f / 1024.0f) - m * m;
    float rs = rsqrtf(va + 1e-5f);
    const float4* sc = (const float4*)(g_ss + b * 2048);
    const float4* sh = (const float4*)(g_ss + b * 2048 + 1024);
    float4 a = sc[tid], d = sh[tid];
    float4 o4;
    o4.x = (v.x - m) * rs * (1.0f + a.x) + d.x;
    o4.y = (v.y - m) * rs * (1.0f + a.y) + d.y;
    o4.z = (v.z - m) * rs * (1.0f + a.z) + d.z;
    o4.w = (v.w - m) * rs * (1.0f + a.w) + d.w;
    ((float4*)(g_x1 + (size_t)bh * 1024))[tid] = o4;
}

// ---------------- channel LayerNorm over H ----------------
__global__ void __launch_bounds__(256) k_chanln(const float* __restrict__ nw,
                                                const float* __restrict__ nb) {
    int b = blockIdx.x;
    int l0 = blockIdx.y * 32;
    int tid = threadIdx.x;
    int lx = tid & 31, hp = tid >> 5;
    float v[32];
    float s = 0.f, q = 0.f;
    const float* base = g_x1 + ((size_t)b * Hh) * Ll + l0 + lx;
    #pragma unroll 8
    for (int k = 0; k < 32; k++) {
        float xv = base[(size_t)(hp * 32 + k) * Ll];
        v[k] = xv; s += xv; q += xv * xv;
    }
    __shared__ float ps[8][32], pq[8][32];
    __shared__ float mean_[32], rstd_[32];
    ps[hp][lx] = s; pq[hp][lx] = q;
    __syncthreads();
    if (tid < 32) {
        float S = 0.f, Q = 0.f;
        #pragma unroll
        for (int p = 0; p < 8; p++) { S += ps[p][tid]; Q += pq[p][tid]; }
        float m  = S * (1.0f / 256.0f);
        float va = Q * (1.0f / 256.0f) - m * m;
        mean_[tid] = m; rstd_[tid] = rsqrtf(va + 1e-5f);
    }
    __syncthreads();
    float m = mean_[lx], r = rstd_[lx];
    float* zb = g_z + ((size_t)b * Hh) * Ll + l0 + lx;
    #pragma unroll 8
    for (int k = 0; k < 32; k++) {
        int h = hp * 32 + k;
        zb[(size_t)h * Ll] = (v[k] - m) * r * nw[h] + nb[h];
    }
}

// ---------------- SSM kernel (time domain, bidirectional assembled) ----------------
__global__ void __launch_bounds__(256) k_ssm(const float* __restrict__ log_dt,
                                             const float* __restrict__ A_re,
                                             const float* __restrict__ A_im,
                                             const float* __restrict__ C_re,
                                             const float* __restrict__ C_im) {
    __shared__ float pre[6][64]; // dtA_re, dtA_im, c0r, c0i, c1r, c1i
    int h = blockIdx.x, tid = threadIdx.x;
    if (tid < 64) {
        int n = tid;
        float dt  = expf(log_dt[h]);
        float are = -expf(A_re[h * 64 + n]);
        float aim = A_im[h * 64 + n];
        float dre = dt * are, dim = dt * aim;
        float er = expf(dre);
        float sn, cs; sincosf(dim, &sn, &cs);
        float dAr = er * cs, dAi = er * sn;
        float numr = dAr - 1.0f, numi = dAi;
        float den = are * are + aim * aim;
        float fr = (numr * are + numi * aim) / den;
        float fi = (numi * are - numr * aim) / den;
        float c0re = C_re[h * 64 + n],             c0im = C_im[h * 64 + n];
        float c1re = C_re[Hh * 64 + h * 64 + n],   c1im = C_im[Hh * 64 + h * 64 + n];
        pre[0][n] = dre; pre[1][n] = dim;
        pre[2][n] = c0re * fr - c0im * fi; pre[3][n] = c0re * fi + c0im * fr;
        pre[4][n] = c1re * fr - c1im * fi; pre[5][n] = c1re * fi + c1im * fr;
    }
    __syncthreads();
    #pragma unroll
    for (int qq = 0; qq < 4; qq++) {
        int l = tid + (qq << 8);
        float lf = (float)l;
        float k0 = 0.f, k1 = 0.f;
        #pragma unroll 4
        for (int n = 0; n < 64; n++) {
            float pr = pre[0][n] * lf, pi = pre[1][n] * lf;
            float e = expf(pr);
            float sn, cs; sincosf(pi, &sn, &cs);
            float vr = e * cs, vi = e * sn;
            k0 += pre[2][n] * vr - pre[3][n] * vi;
            k1 += pre[4][n] * vr - pre[5][n] * vi;
        }
        g_ktime[h * 2048 + l]        = 2.0f * k0;
        g_ktime[h * 2048 + 2047 - l] = 2.0f * k1;
    }
}

// ---------------- radix-8 Stockham FFT, N=2048, 256 threads ----------------
// Stockham: out[R*m*p + r + j*m] = w_N^{j*m*p} * sum_s in[m*p + r + s*N/R] * w_R^{j*s}
// 3 radix-8 stages (m=1,8,64) + 1 twiddle-free radix-4 stage (m=512, p=0).
__device__ __forceinline__ void fft2048_r8(float*& sr, float*& si, float*& dr, float*& di) {
    const float Cq = 0.70710678118654752440f;
    #pragma unroll
    for (int lm = 0; lm < 9; lm += 3) {   // m = 1, 8, 64
        const int m = 1 << lm;
        int i = threadIdx.x;              // one butterfly per thread
        int p = i >> lm;
        int r = i & (m - 1);
        float xr[8], xi[8];
        #pragma unroll
        for (int s = 0; s < 8; s++) { xr[s] = sr[i + (s << 8)]; xi[s] = si[i + (s << 8)]; }
        // layer 1 (distance 4), with w8^s twiddles on the odd branch
        float pr_[4], pi_[4], qr[4], qi[4];
        #pragma unroll
        for (int s = 0; s < 4; s++) {
            pr_[s] = xr[s] + xr[s+4]; pi_[s] = xi[s] + xi[s+4];
            qr[s]  = xr[s] - xr[s+4]; qi[s]  = xi[s] - xi[s+4];
        }
        { float a=qr[1], b=qi[1]; qr[1] = Cq*(a+b); qi[1] = Cq*(b-a); }   // * w8
        { float a=qr[2], b=qi[2]; qr[2] = b;        qi[2] = -a;       }   // * -i
        { float a=qr[3], b=qi[3]; qr[3] = Cq*(b-a); qi[3] = -Cq*(a+b); }  // * w8^3
        float Xr[8], Xi[8];
        { // DFT4 on p -> even outputs
            float r0r=pr_[0]+pr_[2], r0i=pi_[0]+pi_[2];
            float r1r=pr_[0]-pr_[2], r1i=pi_[0]-pi_[2];
            float r2r=pr_[1]+pr_[3], r2i=pi_[1]+pi_[3];
            float t3r=pr_[1]-pr_[3], t3i=pi_[1]-pi_[3];
            float r3r=t3i, r3i=-t3r;
            Xr[0]=r0r+r2r; Xi[0]=r0i+r2i;
            Xr[2]=r1r+r3r; Xi[2]=r1i+r3i;
            Xr[4]=r0r-r2r; Xi[4]=r0i-r2i;
            Xr[6]=r1r-r3r; Xi[6]=r1i-r3i;
        }
        { // DFT4 on q -> odd outputs
            float r0r=qr[0]+qr[2], r0i=qi[0]+qi[2];
            float r1r=qr[0]-qr[2], r1i=qi[0]-qi[2];
            float r2r=qr[1]+qr[3], r2i=qi[1]+qi[3];
            float t3r=qr[1]-qr[3], t3i=qi[1]-qi[3];
            float r3r=t3i, r3i=-t3r;
            Xr[1]=r0r+r2r; Xi[1]=r0i+r2i;
            Xr[3]=r1r+r3r; Xi[3]=r1i+r3i;
            Xr[5]=r0r-r2r; Xi[5]=r0i-r2i;
            Xr[7]=r1r-r3r; Xi[7]=r1i-r3i;
        }
        // output twiddles w^j, w = tw[m*p]
        float2 w = g_tw[m * p];
        float wjr = 1.f, wji = 0.f;
        int o = ((m * p) << 3) + r;
        dr[o] = Xr[0]; di[o] = Xi[0];
        #pragma unroll
        for (int j = 1; j < 8; j++) {
            float nr = wjr * w.x - wji * w.y;
            wji = wji * w.x + wjr * w.y;
            wjr = nr;
            dr[o + j * m] = Xr[j] * wjr - Xi[j] * wji;
            di[o + j * m] = Xi[j] * wjr + Xr[j] * wji;
        }
        __syncthreads();
        float* tp; tp=sr;sr=dr;dr=tp; tp=si;si=di;di=tp;
    }
    // final radix-4, m=512, p=0 (twiddle-free): out[r + j*512] = DFT4_s in[r + 512 s]
    #pragma unroll
    for (int q = 0; q < 2; q++) {
        int r = threadIdx.x + (q << 8);   // 0..511
        float a0r=sr[r],      a0i=si[r];
        float a1r=sr[r+512],  a1i=si[r+512];
        float a2r=sr[r+1024], a2i=si[r+1024];
        float a3r=sr[r+1536], a3i=si[r+1536];
        float r0r=a0r+a2r, r0i=a0i+a2i;
        float r1r=a0r-a2r, r1i=a0i-a2i;
        float r2r=a1r+a3r, r2i=a1i+a3i;
        float t3r=a1r-a3r, t3i=a1i-a3i;
        float r3r=t3i, r3i=-t3r;
        dr[r]      = r0r+r2r; di[r]      = r0i+r2i;
        dr[r+512]  = r1r+r3r; di[r+512]  = r1i+r3i;
        dr[r+1024] = r0r-r2r; di[r+1024] = r0i-r2i;
        dr[r+1536] = r1r-r3r; di[r+1536] = r1i-r3i;
    }
    __syncthreads();
    float* tp; tp=sr;sr=dr;dr=tp; tp=si;si=di;di=tp;
}

// ---------------- FFT of kernel rows (pack 2 h per block, unpack to full spectra) ----------------
__global__ void __launch_bounds__(256) k_kfft() {
    __shared__ float bAr[2048], bAi[2048], bBr[2048], bBi[2048];
    int tid = threadIdx.x;
    int h0 = blockIdx.x * 2, h1 = h0 + 1;
    #pragma unroll
    for (int qq = 0; qq < 8; qq++) {
        int idx = tid + (qq << 8);
        bAr[idx] = g_ktime[h0 * 2048 + idx];
        bAi[idx] = g_ktime[h1 * 2048 + idx];
    }
    __syncthreads();
    float *sr = bAr, *si = bAi, *dr = bBr, *di = bBi;
    fft2048_r8(sr, si, dr, di);
    #pragma unroll
    for (int qq = 0; qq < 8; qq++) {
        int f = tid + (qq << 8);
        int fr2 = (2048 - f) & 2047;
        float ur = sr[f],  ui = si[f];
        float vr = sr[fr2], vi = -si[fr2];
        g_khr[h0 * 2048 + f] = 0.5f * (ur + vr);
        g_khi[h0 * 2048 + f] = 0.5f * (ui + vi);
        g_khr[h1 * 2048 + f] = 0.5f * (ui - vi);
        g_khi[h1 * 2048 + f] = -0.5f * (ur - vr);
    }
}

// ---------------- main conv: 2 batch rows packed; epilogue +D*z, gelu ----------------
__global__ void __launch_bounds__(256) k_conv(const float* __restrict__ Dp) {
    __shared__ float bAr[2048], bAi[2048], bBr[2048], bBi[2048];
    int tid = threadIdx.x;
    int h  = blockIdx.x;
    int pb = blockIdx.y;
    const float* za = g_z + ((size_t)(2 * pb) * Hh + h) * Ll;
    const float* zb = za + (size_t)Hh * Ll;
    float ra[4], rb[4];
    #pragma unroll
    for (int qq = 0; qq < 4; qq++) {
        int idx = tid + (qq << 8);
        ra[qq] = za[idx]; rb[qq] = zb[idx];
        bAr[idx] = ra[qq]; bAi[idx] = rb[qq];
        bAr[idx + 1024] = 0.f; bAi[idx + 1024] = 0.f;
    }
    __syncthreads();
    float *sr = bAr, *si = bAi, *dr = bBr, *di = bBi;
    fft2048_r8(sr, si, dr, di);
    const float* khr = g_khr + h * 2048;
    const float* khi = g_khi + h * 2048;
    const float inv = 1.0f / 2048.0f;
    #pragma unroll
    for (int qq = 0; qq < 8; qq++) {
        int f = tid + (qq << 8);
        float kr = khr[f], ki = khi[f];
        float ar = sr[f], ai = si[f];
        float pr = ar * kr - ai * ki;
        float pi = ar * ki + ai * kr;
        sr[f] = pr * inv;        // conj + scale for inverse transform
        si[f] = -pi * inv;
    }
    __syncthreads();
    fft2048_r8(sr, si, dr, di);
    float Dh = Dp[h];
    float* ya = g_yg + ((size_t)(2 * pb) * Hh + h) * Ll;
    float* yb = ya + (size_t)Hh * Ll;
    #pragma unroll
    for (int qq = 0; qq < 4; qq++) {
        int idx = tid + (qq << 8);
        float v1 = sr[idx]  + Dh * ra[qq];
        float v2 = -si[idx] + Dh * rb[qq];
        ya[idx] = geluf(v1);
        yb[idx] = geluf(v2);
    }
}

// ---------------- tensor-core GEMM (bf16 split precision, fp32 accumulate) ----------------
// C[o,l] = W[o,:]@X[:,l] (+bias)(+resid)(activation)
// Split: w=whi+wlo, x=xhi+xlo (bf16); acc = whi@xhi + whi@xlo + wlo@xhi (fp32).
// 128x128 block tile, 8 warps (2M x 4N), warp tile 64x32, mma.m16n8k16.
// mode 0: gate(acc+b+resid) ; mode 1: acc+b+resid ; mode 2: acc+b
__global__ void __launch_bounds__(256) k_gemm(const float* __restrict__ W,
                                              const float* __restrict__ bias,
                                              const float* __restrict__ X,
                                              const float* __restrict__ resid,
                                              float* __restrict__ Yout,
                                              int mode) {
    __shared__ __nv_bfloat16 Whi[128][24], Wlo[128][24];   // [o][k], stride 24 (bank-safe)
    __shared__ __nv_bfloat16 Xhi[16][136], Xlo[16][136];   // [k][l], stride 136 (bank-safe)
    int l0 = blockIdx.x * 128;
    int o0 = blockIdx.y * 128;
    int b  = blockIdx.z;
    int tid = threadIdx.x;
    int lane = tid & 31, warp = tid >> 5;
    int wm = warp & 1, wn = warp >> 1;        // warp tile: M 64, N 32

    float acc[4][4][4];
    #pragma unroll
    for (int m = 0; m < 4; m++)
        #pragma unroll
        for (int n = 0; n < 4; n++)
            #pragma unroll
            for (int c = 0; c < 4; c++) acc[m][n][c] = 0.f;

    // staging mapping
    int wo = tid >> 1, wk = (tid & 1) * 8;    // W: row wo (128), 8 k
    int xk = tid >> 4, xl = (tid & 15) * 8;   // X: row xk (16),  8 l

    const float* wptr = &W[(size_t)(o0 + wo) * 256 + wk];
    const float* xptr = &X[((size_t)b * Hh + xk) * Ll + l0 + xl];

    float4 w0 = *(const float4*)(wptr);
    float4 w1 = *(const float4*)(wptr + 4);
    float4 x0 = *(const float4*)(xptr);
    float4 x1 = *(const float4*)(xptr + 4);

    #pragma unroll 1
    for (int it = 0; it < 16; it++) {
        {   // convert current chunk to bf16 hi/lo and stage
            float wv[8] = {w0.x,w0.y,w0.z,w0.w,w1.x,w1.y,w1.z,w1.w};
            float xv[8] = {x0.x,x0.y,x0.z,x0.w,x1.x,x1.y,x1.z,x1.w};
            __nv_bfloat16 wh[8], wl[8], xh[8], xlo[8];
            #pragma unroll
            for (int j = 0; j < 8; j++) {
                wh[j] = __float2bfloat16(wv[j]);
                wl[j] = __float2bfloat16(wv[j] - __bfloat162float(wh[j]));
                xh[j] = __float2bfloat16(xv[j]);
                xlo[j] = __float2bfloat16(xv[j] - __bfloat162float(xh[j]));
            }
            *(uint4*)&Whi[wo][wk] = make_uint4(pckbf(wh[0],wh[1]), pckbf(wh[2],wh[3]),
                                               pckbf(wh[4],wh[5]), pckbf(wh[6],wh[7]));
            *(uint4*)&Wlo[wo][wk] = make_uint4(pckbf(wl[0],wl[1]), pckbf(wl[2],wl[3]),
                                               pckbf(wl[4],wl[5]), pckbf(wl[6],wl[7]));
            *(uint4*)&Xhi[xk][xl] = make_uint4(pckbf(xh[0],xh[1]), pckbf(xh[2],xh[3]),
                                               pckbf(xh[4],xh[5]), pckbf(xh[6],xh[7]));
            *(uint4*)&Xlo[xk][xl] = make_uint4(pckbf(xlo[0],xlo[1]), pckbf(xlo[2],xlo[3]),
                                               pckbf(xlo[4],xlo[5]), pckbf(xlo[6],xlo[7]));
        }
        __syncthreads();
        if (it < 15) {
            const float* wp = wptr + (it + 1) * 16;
            const float* xp = xptr + (size_t)(it + 1) * 16 * Ll;
            w0 = *(const float4*)(wp);
            w1 = *(const float4*)(wp + 4);
            x0 = *(const float4*)(xp);
            x1 = *(const float4*)(xp + 4);
        }
        int k0 = (lane & 3) * 2;
        int nb = wn * 32 + (lane >> 2);
        #pragma unroll
        for (int s = 0; s < 3; s++) {
            const __nv_bfloat16 (*Wa)[24]  = (s == 2) ? Wlo : Whi;
            const __nv_bfloat16 (*Xb)[136] = (s == 1) ? Xlo : Xhi;
            unsigned bf[4][2];
            #pragma unroll
            for (int nt = 0; nt < 4; nt++) {
                int n = nb + nt * 8;
                bf[nt][0] = pckbf(Xb[k0][n],     Xb[k0 + 1][n]);
                bf[nt][1] = pckbf(Xb[k0 + 8][n], Xb[k0 + 9][n]);
            }
            #pragma unroll
            for (int m = 0; m < 4; m++) {
                int r = wm * 64 + m * 16 + (lane >> 2);
                unsigned a0 = *(const unsigned*)&Wa[r][k0];
                unsigned a1 = *(const unsigned*)&Wa[r + 8][k0];
                unsigned a2 = *(const unsigned*)&Wa[r][k0 + 8];
                unsigned a3 = *(const unsigned*)&Wa[r + 8][k0 + 8];
                #pragma unroll
                for (int nt = 0; nt < 4; nt++)
                    asm volatile(
                        "mma.sync.aligned.m16n8k16.row.col.f32.bf16.bf16.f32 "
                        "{%0,%1,%2,%3}, {%4,%5,%6,%7}, {%8,%9}, {%0,%1,%2,%3};"
                        : "+f"(acc[m][nt][0]), "+f"(acc[m][nt][1]),
                          "+f"(acc[m][nt][2]), "+f"(acc[m][nt][3])
                        : "r"(a0), "r"(a1), "r"(a2), "r"(a3),
                          "r"(bf[nt][0]), "r"(bf[nt][1]));
            }
        }
        __syncthreads();
    }

    // epilogue
    #pragma unroll
    for (int m = 0; m < 4; m++) {
        int o = o0 + wm * 64 + m * 16 + (lane >> 2);
        float bo0 = bias[o], bo8 = bias[o + 8];
        #pragma unroll
        for (int nt = 0; nt < 4; nt++) {
            int lc = l0 + wn * 32 + nt * 8 + (lane & 3) * 2;
            size_t base0 = ((size_t)b * Hh + o) * Ll + lc;
            size_t base8 = base0 + 8 * (size_t)Ll;
            float v0 = acc[m][nt][0] + bo0;
            float v1 = acc[m][nt][1] + bo0;
            float v2 = acc[m][nt][2] + bo8;
            float v3 = acc[m][nt][3] + bo8;
            if (mode != 2) {
                float2 r0 = *(const float2*)&resid[base0];
                float2 r8 = *(const float2*)&resid[base8];
                v0 += r0.x; v1 += r0.y; v2 += r8.x; v3 += r8.y;
            }
            if (mode == 0) {
                v0 = gatef(v0); v1 = gatef(v1); v2 = gatef(v2); v3 = gatef(v3);
            }
            float2 s0 = make_float2(v0, v1);
            float2 s8 = make_float2(v2, v3);
            *(float2*)&Yout[base0] = s0;
            *(float2*)&Yout[base8] = s8;
        }
    }
}

// ---------------- launch ----------------
extern "C" void kernel_launch(void* const* d_in, const int* in_sizes, int n_in,
                              void* d_out, int out_size) {
    const float* x      = (const float*)d_in[0];
    const int*   t      = (const int*)  d_in[1];
    const float* ada_w  = (const float*)d_in[2];
    const float* ada_b  = (const float*)d_in[3];
    const float* norm_w = (const float*)d_in[4];
    const float* norm_b = (const float*)d_in[5];
    const float* log_dt = (const float*)d_in[6];
    const float* A_re   = (const float*)d_in[7];
    const float* A_im   = (const float*)d_in[8];
    const float* C_re   = (const float*)d_in[9];
    const float* C_im   = (const float*)d_in[10];
    const float* Dp     = (const float*)d_in[11];
    const float* out_w  = (const float*)d_in[12];
    const float* out_b  = (const float*)d_in[13];
    const float* lin1_w = (const float*)d_in[14];
    const float* lin1_b = (const float*)d_in[15];
    const float* lin2_w = (const float*)d_in[16];
    const float* lin2_b = (const float*)d_in[17];
    float* out = (float*)d_out;
    (void)in_sizes; (void)n_in; (void)out_size;

    float *p_x1, *p_z, *p_yg;
    cudaGetSymbolAddress((void**)&p_x1, g_x1);
    cudaGetSymbolAddress((void**)&p_z,  g_z);
    cudaGetSymbolAddress((void**)&p_yg, g_yg);

    k_twfill<<<4, 256>>>();
    k_semb<<<64, 256>>>(t);
    k_ssm<<<256, 256>>>(log_dt, A_re, A_im, C_re, C_im);
    k_kfft<<<128, 256>>>();
    k_ada_gemm<<<dim3(64, 8), 256>>>(ada_w);
    k_ada_reduce<<<512, 256>>>(ada_b);
    k_adaln<<<Bb * Hh, 256>>>(x);
    k_chanln<<<dim3(64, 32), 256>>>(norm_w, norm_b);
    k_conv<<<dim3(256, 32), 256>>>(Dp);
    k_gemm<<<dim3(8, 2, 64), 256>>>(out_w,  out_b,  p_yg, p_x1, p_z,        0);
    k_gemm<<<dim3(8, 2, 64), 256>>>(lin1_w, lin1_b, p_z,  p_x1, out,        1);
    k_gemm<<<dim3(8, 2, 64), 256>>>(lin2_w, lin2_b, p_z,  p_x1, out + BHL,  2);
}